// round 6
// baseline (speedup 1.0000x reference)
#include <cuda_runtime.h>
#include <cstdint>

#define D    64
#define BM   128
#define BN   128
#define PAD  68          // words; 68 mod 32 == 4 -> conflict-free fragment LDS
#define MAXROWS 8192

// ---------------------------------------------------------------------------
__device__ __forceinline__ uint32_t f2tf32(float f) {
    uint32_t u;
    asm("cvt.rna.tf32.f32 %0, %1;" : "=r"(u) : "f"(f));
    return u;
}

// ---------------------------------------------------------------------------
// Fully fused: one 128x128 tile per CTA, 8 warps (2 x 4), warp tile 64x32.
// cross = x1 . x2^T via mma.sync m16n8k8 tf32; row norms computed in-CTA from
// the staged (tf32-rounded) tiles, so d2 == ||x~ - y~||^2 is self-consistent.
// ---------------------------------------------------------------------------
__global__ __launch_bounds__(256, 2)
void dist_kernel(const float* __restrict__ x1, const float* __restrict__ x2,
                 float* __restrict__ out, int M) {
    extern __shared__ uint32_t smem[];
    uint32_t* sa = smem;              // [BM][PAD] tf32 bits
    uint32_t* sb = smem + BM * PAD;   // [BN][PAD]
    float* snrm = (float*)(smem + 2 * BM * PAD);  // [256]: A norms then B norms

    const int n0  = blockIdx.y * BM;
    const int m0  = blockIdx.x * BN;
    const int tid = threadIdx.x;
    const int wid = tid >> 5;
    const int lane = tid & 31;
    const int wm = wid >> 2;          // 0..1 : 64-row band
    const int wn = wid & 3;           // 0..3 : 32-col band
    const int g  = lane >> 2;         // 0..7
    const int q  = lane & 3;          // 0..3

    // ---- stage tiles: gmem float4 -> tf32(RNA) -> smem ----
    {
        const int c4 = (tid & 15) * 4;
        const int rb = tid >> 4;
#pragma unroll
        for (int p = 0; p < 8; ++p) {
            int r = rb + p * 16;
            float4 va = *(const float4*)(x1 + (size_t)(n0 + r) * D + c4);
            float4 vb = *(const float4*)(x2 + (size_t)(m0 + r) * D + c4);
            uint4 ua = make_uint4(f2tf32(va.x), f2tf32(va.y), f2tf32(va.z), f2tf32(va.w));
            uint4 ub = make_uint4(f2tf32(vb.x), f2tf32(vb.y), f2tf32(vb.z), f2tf32(vb.w));
            *(uint4*)(sa + r * PAD + c4) = ua;
            *(uint4*)(sb + r * PAD + c4) = ub;
        }
    }
    __syncthreads();

    // ---- in-CTA row norms from staged tf32 values (1 thread per row) ----
    {
        const uint32_t* rowp = (tid < 128 ? sa : sb) + (tid & 127) * PAD;
        float s = 0.f;
#pragma unroll
        for (int k4 = 0; k4 < 16; ++k4) {
            uint4 u = *(const uint4*)(rowp + k4 * 4);
            float a = __uint_as_float(u.x), b = __uint_as_float(u.y);
            float c = __uint_as_float(u.z), d = __uint_as_float(u.w);
            s = fmaf(a, a, s); s = fmaf(b, b, s);
            s = fmaf(c, c, s); s = fmaf(d, d, s);
        }
        snrm[tid] = s;
    }

    float acc[4][4][4];               // [mf][nf][c0..c3]
#pragma unroll
    for (int i = 0; i < 4; ++i)
#pragma unroll
        for (int j = 0; j < 4; ++j)
#pragma unroll
            for (int c = 0; c < 4; ++c) acc[i][j][c] = 0.f;

    __syncthreads();

    // ---- K loop: 8 steps of k=8 ----
#pragma unroll
    for (int ks = 0; ks < 8; ++ks) {
        const int kb = ks * 8;

        // B fragments: col n = wn*32 + nf*8 + g, k = kb + q (+4)
        uint32_t bfr[4][2];
#pragma unroll
        for (int nf = 0; nf < 4; ++nf) {
            const uint32_t* bp = sb + (wn * 32 + nf * 8 + g) * PAD + kb + q;
            bfr[nf][0] = bp[0];
            bfr[nf][1] = bp[4];
        }

#pragma unroll
        for (int mf = 0; mf < 4; ++mf) {
            const int r = wm * 64 + mf * 16 + g;
            const uint32_t* ap = sa + r * PAD + kb + q;
            uint32_t a0 = ap[0];
            uint32_t a1 = ap[8 * PAD];
            uint32_t a2 = ap[4];
            uint32_t a3 = ap[8 * PAD + 4];
#pragma unroll
            for (int nf = 0; nf < 4; ++nf) {
                asm volatile(
                    "mma.sync.aligned.m16n8k8.row.col.f32.tf32.tf32.f32 "
                    "{%0,%1,%2,%3}, {%4,%5,%6,%7}, {%8,%9}, {%0,%1,%2,%3};"
                    : "+f"(acc[mf][nf][0]), "+f"(acc[mf][nf][1]),
                      "+f"(acc[mf][nf][2]), "+f"(acc[mf][nf][3])
                    : "r"(a0), "r"(a1), "r"(a2), "r"(a3),
                      "r"(bfr[nf][0]), "r"(bfr[nf][1]));
            }
        }
    }

    // ---- epilogue: d2 = max(s1 + s2 - 2*cross, 0), streaming stores ----
    const float* nrmA = snrm;
    const float* nrmB = snrm + 128;
#pragma unroll
    for (int mf = 0; mf < 4; ++mf) {
        const int rloc = wm * 64 + mf * 16 + g;
        const float s1a = nrmA[rloc];
        const float s1b = nrmA[rloc + 8];
        float* orow_a = out + (size_t)(n0 + rloc) * M + m0;
        float* orow_b = orow_a + (size_t)8 * M;
#pragma unroll
        for (int nf = 0; nf < 4; ++nf) {
            const int cidx = wn * 32 + nf * 8 + q * 2;
            const float2 s2 = *(const float2*)&nrmB[cidx];
            float2 ra, rb;
            ra.x = fmaxf(fmaf(-2.f, acc[mf][nf][0], s1a + s2.x), 0.f);
            ra.y = fmaxf(fmaf(-2.f, acc[mf][nf][1], s1a + s2.y), 0.f);
            rb.x = fmaxf(fmaf(-2.f, acc[mf][nf][2], s1b + s2.x), 0.f);
            rb.y = fmaxf(fmaf(-2.f, acc[mf][nf][3], s1b + s2.y), 0.f);
            __stcs((float2*)(orow_a + cidx), ra);
            __stcs((float2*)(orow_b + cidx), rb);
        }
    }
}

// ---------------------------------------------------------------------------
extern "C" void kernel_launch(void* const* d_in, const int* in_sizes, int n_in,
                              void* d_out, int out_size) {
    const float* x1 = (const float*)d_in[0];
    const float* x2 = (const float*)d_in[1];
    float* out = (float*)d_out;

    const int N = in_sizes[0] / D;   // 8192
    const int M = in_sizes[1] / D;   // 8192

    const int smem_bytes = 2 * BM * PAD * sizeof(uint32_t) + 256 * sizeof(float); // 70656
    cudaFuncSetAttribute(dist_kernel,
                         cudaFuncAttributeMaxDynamicSharedMemorySize, smem_bytes);

    dim3 grid(M / BN, N / BM);
    dist_kernel<<<grid, 256, smem_bytes>>>(x1, x2, out, M);
}